// round 1
// baseline (speedup 1.0000x reference)
#include <cuda_runtime.h>

// Problem constants
#define NN   50000
#define EE   800000
#define FE   16
#define RR   4
#define HH   4
#define CC   32
#define HC   128

// ---------------- scratch (static device globals; no allocation) ----------------
__device__ float g_xw[RR * NN * HC];   // per-relation projections [r][n][128]  (102.4MB)
__device__ float g_h[NN * HC];         // layer-1 output (relu)                 (25.6MB)
__device__ float g_qn[RR * NN * HH];   // per-node query logits  [r][n][4]
__device__ float g_kn[RR * NN * HH];   // per-node key logits    [r][n][4]
__device__ float g_ea1[EE * HH];       // edge_attr @ (le1@e1)  [e][4]
__device__ float g_ea3[EE * HH];       // edge_attr @ (le3@e3)  [e][4]
__device__ int   g_deg[NN];
__device__ int   g_rowstart[NN + 1];
__device__ int   g_cursor[NN];
__device__ int2  g_csr[EE];            // { (et<<16)|src , eid } sorted by dst
__device__ float g_M1[FE * HH];
__device__ float g_M3[FE * HH];

// ---------------- CSR build ----------------
__global__ void k_zero_deg() {
    int i = blockIdx.x * blockDim.x + threadIdx.x;
    if (i < NN) g_deg[i] = 0;
}

__global__ void k_hist(const int* __restrict__ ei) {
    int e = blockIdx.x * blockDim.x + threadIdx.x;
    if (e < EE) atomicAdd(&g_deg[ei[EE + e]], 1);
}

// single-block exclusive scan of g_deg -> g_rowstart / g_cursor (N=50000)
__global__ void k_scan() {
    __shared__ int sm[1024];
    __shared__ int s_carry;
    int tid = threadIdx.x;
    if (tid == 0) s_carry = 0;
    __syncthreads();
    const int TILES = (NN + 8191) / 8192;   // 7
    for (int tile = 0; tile < TILES; tile++) {
        int base = tile * 8192 + tid * 8;
        int v[8];
        int tsum = 0;
#pragma unroll
        for (int j = 0; j < 8; j++) {
            int idx = base + j;
            v[j] = (idx < NN) ? g_deg[idx] : 0;
            tsum += v[j];
        }
        sm[tid] = tsum;
        __syncthreads();
        for (int off = 1; off < 1024; off <<= 1) {
            int t = (tid >= off) ? sm[tid - off] : 0;
            __syncthreads();
            sm[tid] += t;
            __syncthreads();
        }
        int excl = s_carry + sm[tid] - tsum;
        int run = excl;
#pragma unroll
        for (int j = 0; j < 8; j++) {
            int idx = base + j;
            if (idx < NN) { g_rowstart[idx] = run; g_cursor[idx] = run; }
            run += v[j];
        }
        __syncthreads();
        if (tid == 0) s_carry += sm[1023];
        __syncthreads();
    }
    if (tid == 0) g_rowstart[NN] = s_carry;   // == EE
}

__global__ void k_scatter(const int* __restrict__ ei, const int* __restrict__ etype) {
    int e = blockIdx.x * blockDim.x + threadIdx.x;
    if (e >= EE) return;
    int d = ei[EE + e];
    int s = ei[e];
    int t = etype[e];
    int pos = atomicAdd(&g_cursor[d], 1);
    g_csr[pos] = make_int2((t << 16) | s, e);
}

// ---------------- M = le @ e  (16x4, both layers) ----------------
__global__ void k_M(const float* __restrict__ le1, const float* __restrict__ e1,
                    const float* __restrict__ le3, const float* __restrict__ e3) {
    int t = threadIdx.x;
    if (t < 64) {
        int f = t >> 2, h = t & 3;
        float s = 0.f;
        for (int c = 0; c < HC; c++) s += le1[f * HC + c] * e1[c * HH + h];
        g_M1[t] = s;
    } else if (t < 128) {
        int u = t - 64;
        int f = u >> 2, h = u & 3;
        float s = 0.f;
        for (int c = 0; c < HC; c++) s += le3[f * HC + c] * e3[c * HH + h];
        g_M3[u] = s;
    }
}

// ---------------- ea = edge_attr @ M  (both layers in one pass) ----------------
__global__ void k_ea(const float* __restrict__ eattr) {
    __shared__ float sM1[64], sM3[64];
    if (threadIdx.x < 64) sM1[threadIdx.x] = g_M1[threadIdx.x];
    else if (threadIdx.x < 128) sM3[threadIdx.x - 64] = g_M3[threadIdx.x - 64];
    __syncthreads();
    int e = blockIdx.x * blockDim.x + threadIdx.x;
    if (e >= EE) return;
    const float* a = eattr + (size_t)e * FE;
    float r1[4] = {0, 0, 0, 0}, r3[4] = {0, 0, 0, 0};
#pragma unroll
    for (int f = 0; f < FE; f++) {
        float v = a[f];
        r1[0] += v * sM1[f * 4 + 0]; r1[1] += v * sM1[f * 4 + 1];
        r1[2] += v * sM1[f * 4 + 2]; r1[3] += v * sM1[f * 4 + 3];
        r3[0] += v * sM3[f * 4 + 0]; r3[1] += v * sM3[f * 4 + 1];
        r3[2] += v * sM3[f * 4 + 2]; r3[3] += v * sM3[f * 4 + 3];
    }
    *(float4*)&g_ea1[(size_t)e * 4] = make_float4(r1[0], r1[1], r1[2], r1[3]);
    *(float4*)&g_ea3[(size_t)e * 4] = make_float4(r3[0], r3[1], r3[2], r3[3]);
}

// ---------------- batched GEMM: xw[r] = X @ W[r], X:[N,128], W[r]:[128,128] ----------------
// grid (ceil(N/64), 4), block 256.  64-row x-tile in smem, W streamed via LDG (L1-hot).
__global__ void k_gemm(const float* __restrict__ xin_arg, const float* __restrict__ w, int layer) {
    __shared__ float xs[64 * 128];
    const float* xin = (layer == 1) ? xin_arg : g_h;
    int r = blockIdx.y;
    int i0 = blockIdx.x * 64;
    int tid = threadIdx.x;
#pragma unroll
    for (int it = 0; it < 8; it++) {
        int q = tid + it * 256;          // float4 index within 64x128 tile
        int row = q >> 5, c4 = q & 31;
        float4 v = make_float4(0.f, 0.f, 0.f, 0.f);
        int gr = i0 + row;
        if (gr < NN) v = *(const float4*)(xin + (size_t)gr * 128 + c4 * 4);
        *(float4*)&xs[row * 128 + c4 * 4] = v;
    }
    __syncthreads();
    int ct = tid & 31, rt = tid >> 5;
    const float4* wp = (const float4*)(w + (size_t)r * 128 * 128);
    float acc[8][4];
#pragma unroll
    for (int i = 0; i < 8; i++)
#pragma unroll
        for (int j = 0; j < 4; j++) acc[i][j] = 0.f;

#pragma unroll 4
    for (int k = 0; k < 128; k++) {
        float4 wv = __ldg(&wp[k * 32 + ct]);
#pragma unroll
        for (int i = 0; i < 8; i++) {
            float xv = xs[(rt * 8 + i) * 128 + k];
            acc[i][0] += xv * wv.x;
            acc[i][1] += xv * wv.y;
            acc[i][2] += xv * wv.z;
            acc[i][3] += xv * wv.w;
        }
    }
#pragma unroll
    for (int i = 0; i < 8; i++) {
        int gr = i0 + rt * 8 + i;
        if (gr < NN)
            *(float4*)&g_xw[((size_t)r * NN + gr) * 128 + ct * 4] =
                make_float4(acc[i][0], acc[i][1], acc[i][2], acc[i][3]);
    }
}

// ---------------- qn/kn = xw @ q, xw @ k  (warp per (r,n) row) ----------------
__global__ void k_qk(const float* __restrict__ q, const float* __restrict__ k) {
    int gw = (blockIdx.x * blockDim.x + threadIdx.x) >> 5;
    int lane = threadIdx.x & 31;
    if (gw >= RR * NN) return;
    const float* xr = g_xw + (size_t)gw * 128;
    float qs[4] = {0, 0, 0, 0}, ks[4] = {0, 0, 0, 0};
#pragma unroll
    for (int j = 0; j < 4; j++) {
        int c = lane + 32 * j;
        float v = xr[c];
        float4 qv = *(const float4*)(q + c * 4);
        float4 kv = *(const float4*)(k + c * 4);
        qs[0] += v * qv.x; qs[1] += v * qv.y; qs[2] += v * qv.z; qs[3] += v * qv.w;
        ks[0] += v * kv.x; ks[1] += v * kv.y; ks[2] += v * kv.z; ks[3] += v * kv.w;
    }
#pragma unroll
    for (int off = 16; off; off >>= 1) {
#pragma unroll
        for (int h = 0; h < 4; h++) {
            qs[h] += __shfl_xor_sync(0xFFFFFFFF, qs[h], off);
            ks[h] += __shfl_xor_sync(0xFFFFFFFF, ks[h], off);
        }
    }
    if (lane == 0) {
        *(float4*)&g_qn[(size_t)gw * 4] = make_float4(qs[0], qs[1], qs[2], qs[3]);
        *(float4*)&g_kn[(size_t)gw * 4] = make_float4(ks[0], ks[1], ks[2], ks[3]);
    }
}

// ---------------- softmax + aggregation: warp per destination node ----------------
// layer==1: writes g_h = relu(agg + b1) (128 channels)
// layer==2: writes out = mean_heads(agg) + b3 (32 channels)
__global__ void k_agg(const float* __restrict__ bias, float* __restrict__ out, int layer) {
    int n = (blockIdx.x * blockDim.x + threadIdx.x) >> 5;
    int lane = threadIdx.x & 31;
    if (n >= NN) return;
    const float* ea = (layer == 1) ? g_ea1 : g_ea3;
    int rs = g_rowstart[n], re = g_rowstart[n + 1];

    float4 qi[4];
#pragma unroll
    for (int r = 0; r < 4; r++) qi[r] = *(const float4*)&g_qn[((size_t)r * NN + n) * 4];

    // pass 1: per-head max of leaky_relu(qi + kj + ea)
    float m0 = -1e30f, m1 = -1e30f, m2 = -1e30f, m3 = -1e30f;
    for (int e = rs; e < re; e++) {
        int2 rec = g_csr[e];
        int et = rec.x >> 16, src = rec.x & 0xFFFF;
        float4 kv = *(const float4*)&g_kn[((size_t)et * NN + src) * 4];
        float4 ev = *(const float4*)&ea[(size_t)rec.y * 4];
        float a0 = qi[et].x + kv.x + ev.x; a0 = a0 > 0.f ? a0 : 0.2f * a0;
        float a1 = qi[et].y + kv.y + ev.y; a1 = a1 > 0.f ? a1 : 0.2f * a1;
        float a2 = qi[et].z + kv.z + ev.z; a2 = a2 > 0.f ? a2 : 0.2f * a2;
        float a3 = qi[et].w + kv.w + ev.w; a3 = a3 > 0.f ? a3 : 0.2f * a3;
        m0 = fmaxf(m0, a0); m1 = fmaxf(m1, a1); m2 = fmaxf(m2, a2); m3 = fmaxf(m3, a3);
    }

    // pass 2: exp, denom, weighted aggregation of xw rows
    float s0 = 0.f, s1 = 0.f, s2 = 0.f, s3 = 0.f;
    float acc0 = 0.f, acc1 = 0.f, acc2 = 0.f, acc3 = 0.f;
    for (int e = rs; e < re; e++) {
        int2 rec = g_csr[e];
        int et = rec.x >> 16, src = rec.x & 0xFFFF;
        float4 kv = *(const float4*)&g_kn[((size_t)et * NN + src) * 4];
        float4 ev = *(const float4*)&ea[(size_t)rec.y * 4];
        float a0 = qi[et].x + kv.x + ev.x; a0 = a0 > 0.f ? a0 : 0.2f * a0;
        float a1 = qi[et].y + kv.y + ev.y; a1 = a1 > 0.f ? a1 : 0.2f * a1;
        float a2 = qi[et].z + kv.z + ev.z; a2 = a2 > 0.f ? a2 : 0.2f * a2;
        float a3 = qi[et].w + kv.w + ev.w; a3 = a3 > 0.f ? a3 : 0.2f * a3;
        float p0 = __expf(a0 - m0), p1 = __expf(a1 - m1);
        float p2 = __expf(a2 - m2), p3 = __expf(a3 - m3);
        s0 += p0; s1 += p1; s2 += p2; s3 += p3;
        const float* xr = g_xw + ((size_t)et * NN + src) * 128 + lane;
        acc0 += p0 * xr[0];
        acc1 += p1 * xr[32];
        acc2 += p2 * xr[64];
        acc3 += p3 * xr[96];
    }

    const float EPS = 1e-16f;
    if (layer == 1) {
        float v0 = acc0 / (s0 + EPS) + bias[lane];
        float v1 = acc1 / (s1 + EPS) + bias[lane + 32];
        float v2 = acc2 / (s2 + EPS) + bias[lane + 64];
        float v3 = acc3 / (s3 + EPS) + bias[lane + 96];
        float* hp = g_h + (size_t)n * 128 + lane;
        hp[0]  = v0 > 0.f ? v0 : 0.f;
        hp[32] = v1 > 0.f ? v1 : 0.f;
        hp[64] = v2 > 0.f ? v2 : 0.f;
        hp[96] = v3 > 0.f ? v3 : 0.f;
    } else {
        float v = 0.25f * (acc0 / (s0 + EPS) + acc1 / (s1 + EPS) +
                           acc2 / (s2 + EPS) + acc3 / (s3 + EPS)) + bias[lane];
        out[(size_t)n * 32 + lane] = v;
    }
}

// ---------------- launch ----------------
extern "C" void kernel_launch(void* const* d_in, const int* in_sizes, int n_in,
                              void* d_out, int out_size) {
    const float* x     = (const float*)d_in[0];
    const int*   ei    = (const int*)  d_in[1];
    const float* eattr = (const float*)d_in[2];
    const int*   etype = (const int*)  d_in[3];
    const float* w1  = (const float*)d_in[4];
    const float* q1  = (const float*)d_in[5];
    const float* k1  = (const float*)d_in[6];
    const float* e1  = (const float*)d_in[7];
    const float* le1 = (const float*)d_in[8];
    const float* b1  = (const float*)d_in[9];
    const float* w3  = (const float*)d_in[10];
    const float* q3  = (const float*)d_in[11];
    const float* k3  = (const float*)d_in[12];
    const float* e3  = (const float*)d_in[13];
    const float* le3 = (const float*)d_in[14];
    const float* b3  = (const float*)d_in[15];
    float* out = (float*)d_out;

    const int EB = (EE + 255) / 256;       // 3125
    const int NB = (NN + 255) / 256;       // 196

    // graph structure (shared by both layers)
    k_zero_deg<<<NB, 256>>>();
    k_hist<<<EB, 256>>>(ei);
    k_scan<<<1, 1024>>>();
    k_scatter<<<EB, 256>>>(ei, etype);
    k_M<<<1, 128>>>(le1, e1, le3, e3);
    k_ea<<<EB, 256>>>(eattr);

    // layer 1
    k_gemm<<<dim3((NN + 63) / 64, RR), 256>>>(x, w1, 1);
    k_qk<<<(RR * NN + 7) / 8, 256>>>(q1, k1);
    k_agg<<<(NN + 7) / 8, 256>>>(b1, out, 1);

    // layer 2
    k_gemm<<<dim3((NN + 63) / 64, RR), 256>>>(x, w3, 2);
    k_qk<<<(RR * NN + 7) / 8, 256>>>(q3, k3);
    k_agg<<<(NN + 7) / 8, 256>>>(b3, out, 2);
}